// round 5
// baseline (speedup 1.0000x reference)
#include <cuda_runtime.h>
#include <math.h>

#define Bq 64
#define Tq 32
#define Eq 512
#define Hq 512
#define H4 2048
#define Vq 10000

// ---------------- scratch (static device globals; no allocation) ----------------
__device__ float g_xs[Tq * Bq * Eq];      // [T][B][E]    4 MB
__device__ float g_xproj[Tq * Bq * H4];   // [T][B][4H]  16 MB
__device__ float g_hseq[Tq * Bq * Hq];    // [T][B][H]    4 MB
__device__ float g_h[2][Bq * Hq];         // double-buffered hidden state
__device__ float g_c[Bq * Hq];            // cell state
__device__ float g_WhhT[Hq * H4];         // W_hh transposed: [K=512][4H=2048]
__device__ float g_bias[H4];              // b_ih + b_hh
__device__ int   g_tok[Bq * Tq];          // decoded caption tokens (dtype-robust)

// ---------------- token decode: handle captions as int32 OR int64 ---------------
// View buffer as int32. If the true dtype is int64 (little-endian), every odd
// int32 is a high word == 0 (tokens are in [0, V)). With random int32 tokens,
// P(all 1024 odd slots == 0) ~ 0. We only read the first 2048 int32s here,
// which is in-bounds for either dtype.
__global__ void k_tok(const int* __restrict__ cap32) {
    __shared__ int s_or;
    if (threadIdx.x == 0) s_or = 0;
    __syncthreads();
    int tid = threadIdx.x;                 // 1024 threads
    if (cap32[2 * tid + 1] != 0) atomicOr(&s_or, 1);
    __syncthreads();
    bool is64 = (s_or == 0);
    for (int i = tid; i < Bq * Tq; i += 1024) {
        int tok = is64 ? cap32[2 * i] : cap32[i];
        // clamp defensively: a bad token becomes a wrong value, not a crash
        tok = tok < 0 ? 0 : (tok >= Vq ? Vq - 1 : tok);
        g_tok[i] = tok;
    }
}

// ---------------- prep: gather embeddings, zero state, combine biases ------------
__global__ void k_prep(const float* __restrict__ feat,
                       const float* __restrict__ embW,
                       const float* __restrict__ b_ih,
                       const float* __restrict__ b_hh) {
    int i = blockIdx.x * blockDim.x + threadIdx.x;   // 262144 threads: one float4 of xs each
    int e4 = i & 127;            // E/4 = 128
    int b  = (i >> 7) & 63;
    int t  = i >> 13;
    float4 v;
    if (t == 0) {
        v = ((const float4*)feat)[b * 128 + e4];
    } else {
        int tok = g_tok[b * Tq + t];
        v = ((const float4*)embW)[(size_t)tok * 128 + e4];
    }
    ((float4*)g_xs)[i] = v;

    if (i < (Bq * Hq) / 4) {
        ((float4*)g_h[0])[i] = make_float4(0.f, 0.f, 0.f, 0.f);
        ((float4*)g_c)[i]    = make_float4(0.f, 0.f, 0.f, 0.f);
    }
    if (i < H4) g_bias[i] = b_ih[i] + b_hh[i];
}

// ---------------- transpose W_hh [2048][512] -> g_WhhT [512][2048] ---------------
__global__ void k_transpose(const float* __restrict__ W) {
    __shared__ float tile[32][33];
    int k0 = blockIdx.x * 32;    // K dim (512)
    int n0 = blockIdx.y * 32;    // 4H dim (2048)
    int tx = threadIdx.x, ty = threadIdx.y;   // (32, 8)
    #pragma unroll
    for (int r = 0; r < 4; r++)
        tile[ty + 8 * r][tx] = W[(size_t)(n0 + ty + 8 * r) * Hq + k0 + tx];
    __syncthreads();
    #pragma unroll
    for (int r = 0; r < 4; r++)
        g_WhhT[(size_t)(k0 + ty + 8 * r) * H4 + n0 + tx] = tile[tx][ty + 8 * r];
}

// ---------------- SGEMM: C = A(MxK) * B(NxK)^T + bias ---------------------------
// 128x128 block tile, BK=8, 8x8 register tile per thread, 256 threads.
// MODE 0: C[m*N + n]          (x_proj)
// MODE 1: out[(m%64)*T*V + (m/64)*V + n]   (fc logits scatter to [B][T][V])
template <int MODE>
__global__ void __launch_bounds__(256, 2)
k_sgemm(const float* __restrict__ A, const float* __restrict__ Bw,
        const float* __restrict__ bias, float* __restrict__ C,
        int N, int K) {
    __shared__ float As[8][132];
    __shared__ float Bs[8][132];
    const int tid = threadIdx.x;
    const int bm = blockIdx.y * 128;
    const int bn = blockIdx.x * 128;

    const int lRow = tid >> 1;           // 0..127
    const int lSeg = (tid & 1) * 4;      // 0 or 4
    const int tRow = (tid >> 4) * 8;     // 0..120
    const int tCol = (tid & 15) * 8;     // 0..120

    float acc[8][8];
    #pragma unroll
    for (int i = 0; i < 8; i++)
        #pragma unroll
        for (int j = 0; j < 8; j++) acc[i][j] = 0.f;

    const float* Aptr = A + (size_t)(bm + lRow) * K + lSeg;
    const bool bvalid = (bn + lRow) < N;
    const float* Bptr = Bw + (size_t)(bn + lRow) * K + lSeg;

    for (int k0 = 0; k0 < K; k0 += 8) {
        float4 av = *(const float4*)(Aptr + k0);
        float4 bv = bvalid ? *(const float4*)(Bptr + k0) : make_float4(0.f, 0.f, 0.f, 0.f);
        As[lSeg + 0][lRow] = av.x; As[lSeg + 1][lRow] = av.y;
        As[lSeg + 2][lRow] = av.z; As[lSeg + 3][lRow] = av.w;
        Bs[lSeg + 0][lRow] = bv.x; Bs[lSeg + 1][lRow] = bv.y;
        Bs[lSeg + 2][lRow] = bv.z; Bs[lSeg + 3][lRow] = bv.w;
        __syncthreads();
        #pragma unroll
        for (int kk = 0; kk < 8; kk++) {
            float ra[8], rb[8];
            #pragma unroll
            for (int i = 0; i < 8; i++) ra[i] = As[kk][tRow + i];
            #pragma unroll
            for (int j = 0; j < 8; j++) rb[j] = Bs[kk][tCol + j];
            #pragma unroll
            for (int i = 0; i < 8; i++)
                #pragma unroll
                for (int j = 0; j < 8; j++)
                    acc[i][j] = fmaf(ra[i], rb[j], acc[i][j]);
        }
        __syncthreads();
    }

    #pragma unroll
    for (int i = 0; i < 8; i++) {
        int m = bm + tRow + i;
        #pragma unroll
        for (int j = 0; j < 8; j++) {
            int n = bn + tCol + j;
            if (n < N) {
                float val = acc[i][j] + bias[n];
                if (MODE == 0)
                    C[(size_t)m * N + n] = val;
                else
                    C[(size_t)(m & 63) * (Tq * Vq) + (size_t)(m >> 6) * Vq + n] = val;
            }
        }
    }
}

// ---------------- fused LSTM step: gates GEMM + nonlinearity + state update -----
// grid = 32 blocks (j-chunks of 16), 256 threads.
// thread (jl, b0) owns outputs h[b0..b0+3][j0+jl]; computes all 4 gate dots.
__global__ void __launch_bounds__(256) k_lstm(int t) {
    __shared__ float Hs[64][65];   // h_prev[b][k] chunk
    __shared__ float Ws[64][65];   // W_hhT[k][gate*16 + jl] chunk
    const int tid = threadIdx.x;
    const int jl = tid & 15;
    const int b0 = (tid >> 4) * 4;
    const int j0 = blockIdx.x * 16;
    const float* __restrict__ hprev = g_h[t & 1];

    float acc[4][4];   // [gate][bb]
    #pragma unroll
    for (int g = 0; g < 4; g++)
        #pragma unroll
        for (int bb = 0; bb < 4; bb++) acc[g][bb] = 0.f;

    for (int kc = 0; kc < Hq; kc += 64) {
        #pragma unroll
        for (int r = 0; r < 16; r++) {
            int idx = r * 256 + tid;
            int row = idx >> 6, col = idx & 63;
            Hs[row][col] = hprev[row * Hq + kc + col];
            Ws[row][col] = g_WhhT[(size_t)(kc + row) * H4 + (col >> 4) * Hq + j0 + (col & 15)];
        }
        __syncthreads();
        #pragma unroll 8
        for (int kk = 0; kk < 64; kk++) {
            float w0 = Ws[kk][jl];
            float w1 = Ws[kk][16 + jl];
            float w2 = Ws[kk][32 + jl];
            float w3 = Ws[kk][48 + jl];
            #pragma unroll
            for (int bb = 0; bb < 4; bb++) {
                float hv = Hs[b0 + bb][kk];
                acc[0][bb] = fmaf(w0, hv, acc[0][bb]);
                acc[1][bb] = fmaf(w1, hv, acc[1][bb]);
                acc[2][bb] = fmaf(w2, hv, acc[2][bb]);
                acc[3][bb] = fmaf(w3, hv, acc[3][bb]);
            }
        }
        __syncthreads();
    }

    const int j = j0 + jl;
    const float* __restrict__ xp = g_xproj + (size_t)t * Bq * H4;
    float* __restrict__ hnext = g_h[(t + 1) & 1];
    float* __restrict__ hs = g_hseq + (size_t)t * Bq * Hq;
    #pragma unroll
    for (int bb = 0; bb < 4; bb++) {
        int b = b0 + bb;
        float gi = acc[0][bb] + xp[b * H4 + j];
        float gf = acc[1][bb] + xp[b * H4 + Hq + j];
        float gg = acc[2][bb] + xp[b * H4 + 2 * Hq + j];
        float go = acc[3][bb] + xp[b * H4 + 3 * Hq + j];
        float si = 1.f / (1.f + expf(-gi));
        float sf = 1.f / (1.f + expf(-gf));
        float so = 1.f / (1.f + expf(-go));
        float cn = sf * g_c[b * Hq + j] + si * tanhf(gg);
        float hn = so * tanhf(cn);
        g_c[b * Hq + j] = cn;
        hnext[b * Hq + j] = hn;
        hs[b * Hq + j] = hn;
    }
}

// ---------------- launch --------------------------------------------------------
extern "C" void kernel_launch(void* const* d_in, const int* in_sizes, int n_in,
                              void* d_out, int out_size) {
    const float* feat = (const float*)d_in[0];
    const int*   cap  = (const int*)d_in[1];     // int32 OR int64 — detected on device
    const float* embW = (const float*)d_in[2];
    const float* W_ih = (const float*)d_in[3];
    const float* W_hh = (const float*)d_in[4];
    const float* b_ih = (const float*)d_in[5];
    const float* b_hh = (const float*)d_in[6];
    const float* fc_W = (const float*)d_in[7];
    const float* fc_b = (const float*)d_in[8];
    float* out = (float*)d_out;

    float *p_xs, *p_xproj, *p_hseq, *p_bias;
    cudaGetSymbolAddress((void**)&p_xs,    g_xs);
    cudaGetSymbolAddress((void**)&p_xproj, g_xproj);
    cudaGetSymbolAddress((void**)&p_hseq,  g_hseq);
    cudaGetSymbolAddress((void**)&p_bias,  g_bias);

    // 0. decode caption tokens (robust to int32 vs int64)
    k_tok<<<1, 1024>>>(cap);
    // 1. gather xs + zero state + combined bias
    k_prep<<<1024, 256>>>(feat, embW, b_ih, b_hh);
    // 2. transpose W_hh for the scan
    k_transpose<<<dim3(16, 64), dim3(32, 8)>>>(W_hh);
    // 3. x_proj = xs @ W_ih^T + (b_ih + b_hh)     M=2048, N=2048, K=512
    k_sgemm<0><<<dim3(16, 16), 256>>>(p_xs, W_ih, p_bias, p_xproj, H4, Eq);
    // 4. LSTM scan: 32 fused steps
    for (int t = 0; t < Tq; t++)
        k_lstm<<<32, 256>>>(t);
    // 5. logits = h_seq @ fc_W^T + fc_b, scattered to [B][T][V]   M=2048, N=10000, K=512
    k_sgemm<1><<<dim3((Vq + 127) / 128, 16), 256>>>(p_hseq, fc_W, fc_b, out, Vq, Eq);
}

// round 9
// speedup vs baseline: 2.3805x; 2.3805x over previous
#include <cuda_runtime.h>
#include <cuda_bf16.h>
#include <math.h>
#include <stdint.h>

#define Bq 64
#define Tq 32
#define Eq 512
#define Hq 512
#define H4 2048
#define Vq 10000

// ---------------- scratch (static device globals; no allocation) ----------------
__device__ __nv_bfloat16 g_xs_h[Tq * Bq * Eq];    // xs split hi   2MB
__device__ __nv_bfloat16 g_xs_l[Tq * Bq * Eq];    // xs split lo   2MB
__device__ __nv_bfloat16 g_wih_h[H4 * Eq];        // W_ih split    2MB
__device__ __nv_bfloat16 g_wih_l[H4 * Eq];
__device__ __nv_bfloat16 g_fcw_h[Vq * Hq];        // fc_W split   10MB
__device__ __nv_bfloat16 g_fcw_l[Vq * Hq];
__device__ __nv_bfloat16 g_hs_h[Tq * Bq * Hq];    // h_seq split   2MB
__device__ __nv_bfloat16 g_hs_l[Tq * Bq * Hq];
__device__ float g_xproj[Tq * Bq * H4];           // [T][B][4H]   16MB
__device__ float g_hbuf[2][Bq * Hq];              // double-buffered hidden state
__device__ float g_bias[H4];                      // b_ih + b_hh
__device__ int   g_tok[Bq * Tq];                  // decoded caption tokens
__device__ unsigned g_cnt;                        // grid barrier counter
__device__ volatile unsigned g_gen;               // grid barrier generation

// ---------------- helpers -------------------------------------------------------
__device__ __forceinline__ uint32_t smem_u32(const void* p) {
    uint32_t a;
    asm("{ .reg .u64 t; cvta.to.shared.u64 t, %1; cvt.u32.u64 %0, t; }" : "=r"(a) : "l"(p));
    return a;
}

#define LDSM4(r, addr) \
    asm volatile("ldmatrix.sync.aligned.m8n8.x4.shared.b16 {%0,%1,%2,%3}, [%4];" \
        : "=r"((r)[0]), "=r"((r)[1]), "=r"((r)[2]), "=r"((r)[3]) : "r"(addr))

#define MMA16816(d, a, b) \
    asm volatile("mma.sync.aligned.m16n8k16.row.col.f32.bf16.bf16.f32 " \
        "{%0,%1,%2,%3}, {%4,%5,%6,%7}, {%8,%9}, {%0,%1,%2,%3};" \
        : "+f"((d)[0]), "+f"((d)[1]), "+f"((d)[2]), "+f"((d)[3]) \
        : "r"((a)[0]), "r"((a)[1]), "r"((a)[2]), "r"((a)[3]), "r"((b)[0]), "r"((b)[1]))

__device__ __forceinline__ void split1(float x, __nv_bfloat16& h, __nv_bfloat16& l) {
    h = __float2bfloat16(x);
    l = __float2bfloat16(x - __bfloat162float(h));
}

// ---------------- token decode: handle captions as int32 OR int64 ---------------
__global__ void k_tok(const int* __restrict__ cap32) {
    __shared__ int s_or;
    if (threadIdx.x == 0) s_or = 0;
    __syncthreads();
    int tid = threadIdx.x;                 // 1024 threads
    if (cap32[2 * tid + 1] != 0) atomicOr(&s_or, 1);
    __syncthreads();
    bool is64 = (s_or == 0);
    for (int i = tid; i < Bq * Tq; i += 1024) {
        int tok = is64 ? cap32[2 * i] : cap32[i];
        tok = tok < 0 ? 0 : (tok >= Vq ? Vq - 1 : tok);
        g_tok[i] = tok;
    }
}

// ---------------- prep: gather embeddings (split to bf16 hi/lo), bias, barrier --
__global__ void k_prep(const float* __restrict__ feat,
                       const float* __restrict__ embW,
                       const float* __restrict__ b_ih,
                       const float* __restrict__ b_hh) {
    int i = blockIdx.x * blockDim.x + threadIdx.x;   // 262144: one float4 of xs each
    int e4 = i & 127;            // E/4 = 128
    int b  = (i >> 7) & 63;
    int t  = i >> 13;
    float4 v;
    if (t == 0) {
        v = ((const float4*)feat)[b * 128 + e4];
    } else {
        int tok = g_tok[b * Tq + t];
        v = ((const float4*)embW)[(size_t)tok * 128 + e4];
    }
    __nv_bfloat16 h0, l0, h1, l1, h2, l2, h3, l3;
    split1(v.x, h0, l0); split1(v.y, h1, l1);
    split1(v.z, h2, l2); split1(v.w, h3, l3);
    ((ushort4*)g_xs_h)[i] = make_ushort4(__bfloat16_as_ushort(h0), __bfloat16_as_ushort(h1),
                                         __bfloat16_as_ushort(h2), __bfloat16_as_ushort(h3));
    ((ushort4*)g_xs_l)[i] = make_ushort4(__bfloat16_as_ushort(l0), __bfloat16_as_ushort(l1),
                                         __bfloat16_as_ushort(l2), __bfloat16_as_ushort(l3));

    if (i < H4) g_bias[i] = b_ih[i] + b_hh[i];
    if (i == 0) { g_cnt = 0; g_gen = 0; }
}

// ---------------- generic fp32 -> bf16 hi/lo split -------------------------------
__global__ void k_split(const float* __restrict__ in, __nv_bfloat16* __restrict__ oh,
                        __nv_bfloat16* __restrict__ ol, int n4) {
    int i = blockIdx.x * blockDim.x + threadIdx.x;
    if (i >= n4) return;
    float4 v = ((const float4*)in)[i];
    __nv_bfloat16 h0, l0, h1, l1, h2, l2, h3, l3;
    split1(v.x, h0, l0); split1(v.y, h1, l1);
    split1(v.z, h2, l2); split1(v.w, h3, l3);
    ((ushort4*)oh)[i] = make_ushort4(__bfloat16_as_ushort(h0), __bfloat16_as_ushort(h1),
                                     __bfloat16_as_ushort(h2), __bfloat16_as_ushort(h3));
    ((ushort4*)ol)[i] = make_ushort4(__bfloat16_as_ushort(l0), __bfloat16_as_ushort(l1),
                                     __bfloat16_as_ushort(l2), __bfloat16_as_ushort(l3));
}

// ---------------- HMMA bf16 3-pass GEMM: C = A*B^T + bias -----------------------
// Block tile 128x128, BK=32, 8 warps of 32m x 64n. cp.async double-buffered smem,
// XOR-16B swizzle, ldmatrix.x4 fragments, mma.sync.m16n8k16 (baseline PTX ISA).
// Precision: A=Ah+Al, B=Bh+Bl (bf16); acc += Ah*Bh + Ah*Bl + Al*Bh in fp32.
// MODE 0: C[m*2048 + n]                          (x_proj)
// MODE 1: out[(m&63)*T*V + (m>>6)*V + n], n<Nn   (fc logits scatter to [B][T][V])
#define TILE_A_H 0
#define TILE_A_L 8192
#define TILE_B_H 16384
#define TILE_B_L 24576
#define BUF_STRIDE 32768
#define SMEM_TOTAL 65536
#define NKB 16

template <int MODE>
__global__ void __launch_bounds__(256, 1)
k_mma(const __nv_bfloat16* __restrict__ Ah, const __nv_bfloat16* __restrict__ Al,
      const __nv_bfloat16* __restrict__ Bh, const __nv_bfloat16* __restrict__ Bl,
      const float* __restrict__ bias, float* __restrict__ C, int Nn) {
    extern __shared__ char smem[];
    const uint32_t sb = smem_u32(smem);
    const int tid  = threadIdx.x;
    const int lane = tid & 31;
    const int wid  = tid >> 5;
    const int bm = blockIdx.y * 128;
    const int bn = blockIdx.x * 128;
    const int m0 = (wid & 3) * 32;     // warp m-offset within tile
    const int n0 = (wid >> 2) * 64;    // warp n-offset within tile

    float acc[2][8][4];
    #pragma unroll
    for (int ma = 0; ma < 2; ma++)
        #pragma unroll
        for (int na = 0; na < 8; na++)
            #pragma unroll
            for (int q = 0; q < 4; q++) acc[ma][na][q] = 0.f;

    auto fill = [&](int kb, int buf) {
        #pragma unroll
        for (int i = 0; i < 8; i++) {
            int q = tid + i * 256;           // 0..2047 chunk id
            int tile = q >> 9;               // 0..3 (Ah, Al, Bh, Bl)
            int w = q & 511;
            int row = w >> 2, c = w & 3;
            uint32_t dst = sb + (uint32_t)buf * BUF_STRIDE + (uint32_t)tile * 8192
                         + (uint32_t)(row * 64) + (uint32_t)((c ^ (row & 3)) << 4);
            int kc = kb * 32 + c * 8;
            const __nv_bfloat16* src;
            bool valid = true;
            if (tile == 0)      src = Ah + (size_t)(bm + row) * 512 + kc;
            else if (tile == 1) src = Al + (size_t)(bm + row) * 512 + kc;
            else {
                valid = (MODE == 0) || (bn + row) < Nn;
                src = (tile == 2 ? Bh : Bl) + (size_t)(bn + row) * 512 + kc;
            }
            if (valid)
                asm volatile("cp.async.cg.shared.global [%0], [%1], 16;"
                             :: "r"(dst), "l"(src));
            else
                asm volatile("st.shared.v4.b32 [%0], {%1,%1,%1,%1};" :: "r"(dst), "r"(0u));
        }
    };

    auto compute = [&](int buf) {
        const uint32_t bb = sb + (uint32_t)buf * BUF_STRIDE;
        #pragma unroll
        for (int ka = 0; ka < 2; ka++) {
            // B fragments: 8 n-atoms, hi+lo. x4 covers 2 n-atoms (n16 x k16).
            uint32_t bhf[8][2], blf[8][2];
            const int brow0 = n0 + (lane & 7) + ((lane >> 4) & 1) * 8;
            const int bck = ka * 2 + ((lane >> 3) & 1);
            #pragma unroll
            for (int g = 0; g < 4; g++) {
                int row = brow0 + g * 16;
                uint32_t off = (uint32_t)(row * 64) + (uint32_t)((bck ^ (row & 3)) << 4);
                uint32_t r[4];
                LDSM4(r, bb + TILE_B_H + off);
                bhf[2*g][0] = r[0]; bhf[2*g][1] = r[1];
                bhf[2*g+1][0] = r[2]; bhf[2*g+1][1] = r[3];
                LDSM4(r, bb + TILE_B_L + off);
                blf[2*g][0] = r[0]; blf[2*g][1] = r[1];
                blf[2*g+1][0] = r[2]; blf[2*g+1][1] = r[3];
            }
            // A fragments: 2 m-atoms (m16 x k16 each), hi+lo.
            uint32_t ahf[2][4], alf[2][4];
            const int arow0 = m0 + (lane & 15);
            const int ack = ka * 2 + (lane >> 4);
            #pragma unroll
            for (int ma = 0; ma < 2; ma++) {
                int row = arow0 + ma * 16;
                uint32_t off = (uint32_t)(row * 64) + (uint32_t)((ack ^ (row & 3)) << 4);
                LDSM4(ahf[ma], bb + TILE_A_H + off);
                LDSM4(alf[ma], bb + TILE_A_L + off);
            }
            #pragma unroll
            for (int ma = 0; ma < 2; ma++)
                #pragma unroll
                for (int na = 0; na < 8; na++) {
                    MMA16816(acc[ma][na], ahf[ma], bhf[na]);   // hi*hi
                    MMA16816(acc[ma][na], ahf[ma], blf[na]);   // hi*lo
                    MMA16816(acc[ma][na], alf[ma], bhf[na]);   // lo*hi
                }
        }
    };

    fill(0, 0);
    asm volatile("cp.async.commit_group;" ::: "memory");
    for (int kb = 0; kb < NKB; kb++) {
        if (kb + 1 < NKB) {
            fill(kb + 1, (kb + 1) & 1);
            asm volatile("cp.async.commit_group;" ::: "memory");
            asm volatile("cp.async.wait_group 1;" ::: "memory");
        } else {
            asm volatile("cp.async.wait_group 0;" ::: "memory");
        }
        __syncthreads();
        compute(kb & 1);
        __syncthreads();
    }

    // epilogue: c-frag thread T holds rows T/4 and T/4+8, cols 2*(T%4)..+1
    #pragma unroll
    for (int ma = 0; ma < 2; ma++)
        #pragma unroll
        for (int na = 0; na < 8; na++) {
            int mrow0 = bm + m0 + ma * 16 + (lane >> 2);
            int n = bn + n0 + na * 8 + (lane & 3) * 2;
            if (MODE == 1 && n >= Nn) continue;
            float2 bv = *(const float2*)(bias + n);
            #pragma unroll
            for (int half = 0; half < 2; half++) {
                int m = mrow0 + half * 8;
                size_t base = (MODE == 0)
                    ? (size_t)m * 2048 + n
                    : (size_t)(m & 63) * (Tq * (size_t)Vq) + (size_t)(m >> 6) * Vq + n;
                float2 o;
                o.x = acc[ma][na][half * 2 + 0] + bv.x;
                o.y = acc[ma][na][half * 2 + 1] + bv.y;
                *(float2*)(C + base) = o;
            }
        }
}

// ---------------- persistent LSTM scan ------------------------------------------
// 128 blocks (all resident on 148 SMs), 256 threads. Block owns 4 j-columns.
// Thread (b, jl) owns (h, c) for one (batch, j); c lives in a register.
// Weights (16 gate-rows x 512) loaded ONCE into smem, reused for all 32 steps.
__device__ __forceinline__ void gridsync(unsigned gen) {
    __syncthreads();
    if (threadIdx.x == 0) {
        __threadfence();
        if (atomicAdd(&g_cnt, 1) == 127u) {
            g_cnt = 0;
            __threadfence();
            g_gen = gen;
        } else {
            while (g_gen != gen) __nanosleep(32);
            __threadfence();
        }
    }
    __syncthreads();
}

__global__ void __launch_bounds__(256, 1) k_scan(const float* __restrict__ Whh) {
    __shared__ float w_s[16][516];   // [g*4+jl][k], padded: conflict-free across jl
    const int tid = threadIdx.x;
    const int jl = tid & 3;
    const int b_ = tid >> 2;         // 0..63
    const int j0 = blockIdx.x * 4;
    const int j  = j0 + jl;

    { // load this block's W_hh slice: rows g*512 + j0 + jl' (k-contiguous in W_hh)
        int c = tid >> 4, seg = tid & 15;
        int grow = (c >> 2) * Hq + j0 + (c & 3);
        const float4* src = (const float4*)(Whh + (size_t)grow * Hq);
        #pragma unroll
        for (int i = 0; i < 8; i++) {
            int f4 = seg + i * 16;
            *(float4*)&w_s[c][f4 * 4] = src[f4];
        }
    }
    __syncthreads();

    float c_reg = 0.f;
    for (int t = 0; t < Tq; t++) {
        float a0 = 0.f, a1 = 0.f, a2 = 0.f, a3 = 0.f;
        if (t > 0) {
            const float4* hp = (const float4*)(g_hbuf[t & 1] + b_ * Hq);
            #pragma unroll 2
            for (int k4 = 0; k4 < 128; k4++) {
                float4 hv = __ldcg(hp + k4);                   // L2 (coherent across SMs)
                float4 w0 = *(const float4*)&w_s[jl][k4 * 4];
                float4 w1 = *(const float4*)&w_s[4 + jl][k4 * 4];
                float4 w2 = *(const float4*)&w_s[8 + jl][k4 * 4];
                float4 w3 = *(const float4*)&w_s[12 + jl][k4 * 4];
                a0 = fmaf(hv.x, w0.x, a0); a0 = fmaf(hv.y, w0.y, a0);
                a0 = fmaf(hv.z, w0.z, a0); a0 = fmaf(hv.w, w0.w, a0);
                a1 = fmaf(hv.x, w1.x, a1); a1 = fmaf(hv.y, w1.y, a1);
                a1 = fmaf(hv.z, w1.z, a1); a1 = fmaf(hv.w, w1.w, a1);
                a2 = fmaf(hv.x, w2.x, a2); a2 = fmaf(hv.y, w2.y, a2);
                a2 = fmaf(hv.z, w2.z, a2); a2 = fmaf(hv.w, w2.w, a2);
                a3 = fmaf(hv.x, w3.x, a3); a3 = fmaf(hv.y, w3.y, a3);
                a3 = fmaf(hv.z, w3.z, a3); a3 = fmaf(hv.w, w3.w, a3);
            }
        }
        const float* xp = g_xproj + (size_t)t * Bq * H4 + (size_t)b_ * H4;
        float gi = a0 + __ldg(xp + j);
        float gf = a1 + __ldg(xp + Hq + j);
        float gg = a2 + __ldg(xp + 2 * Hq + j);
        float go = a3 + __ldg(xp + 3 * Hq + j);
        float si = 1.f / (1.f + __expf(-gi));
        float sf = 1.f / (1.f + __expf(-gf));
        float so = 1.f / (1.f + __expf(-go));
        c_reg = sf * c_reg + si * tanhf(gg);
        float hn = so * tanhf(c_reg);
        g_hbuf[(t + 1) & 1][b_ * Hq + j] = hn;
        __nv_bfloat16 hh, hl;
        split1(hn, hh, hl);
        size_t mi = (size_t)(t * Bq + b_) * Hq + j;
        g_hs_h[mi] = hh;
        g_hs_l[mi] = hl;
        if (t < Tq - 1) gridsync((unsigned)(t + 1));
    }
}

// ---------------- launch --------------------------------------------------------
extern "C" void kernel_launch(void* const* d_in, const int* in_sizes, int n_in,
                              void* d_out, int out_size) {
    const float* feat = (const float*)d_in[0];
    const int*   cap  = (const int*)d_in[1];     // int32 OR int64 — detected on device
    const float* embW = (const float*)d_in[2];
    const float* W_ih = (const float*)d_in[3];
    const float* W_hh = (const float*)d_in[4];
    const float* b_ih = (const float*)d_in[5];
    const float* b_hh = (const float*)d_in[6];
    const float* fc_W = (const float*)d_in[7];
    const float* fc_b = (const float*)d_in[8];
    float* out = (float*)d_out;

    static int smem_set = 0;
    if (!smem_set) {
        cudaFuncSetAttribute(k_mma<0>, cudaFuncAttributeMaxDynamicSharedMemorySize, SMEM_TOTAL);
        cudaFuncSetAttribute(k_mma<1>, cudaFuncAttributeMaxDynamicSharedMemorySize, SMEM_TOTAL);
        smem_set = 1;
    }

    __nv_bfloat16 *p_xs_h, *p_xs_l, *p_wih_h, *p_wih_l, *p_fcw_h, *p_fcw_l, *p_hs_h, *p_hs_l;
    float *p_xproj, *p_bias;
    cudaGetSymbolAddress((void**)&p_xs_h,  g_xs_h);
    cudaGetSymbolAddress((void**)&p_xs_l,  g_xs_l);
    cudaGetSymbolAddress((void**)&p_wih_h, g_wih_h);
    cudaGetSymbolAddress((void**)&p_wih_l, g_wih_l);
    cudaGetSymbolAddress((void**)&p_fcw_h, g_fcw_h);
    cudaGetSymbolAddress((void**)&p_fcw_l, g_fcw_l);
    cudaGetSymbolAddress((void**)&p_hs_h,  g_hs_h);
    cudaGetSymbolAddress((void**)&p_hs_l,  g_hs_l);
    cudaGetSymbolAddress((void**)&p_xproj, g_xproj);
    cudaGetSymbolAddress((void**)&p_bias,  g_bias);

    // 0. decode caption tokens (robust to int32 vs int64)
    k_tok<<<1, 1024>>>(cap);
    // 1. gather xs -> bf16 hi/lo split, combined bias, barrier reset
    k_prep<<<1024, 256>>>(feat, embW, b_ih, b_hh);
    // 2. split weights to bf16 hi/lo
    k_split<<<1024, 256>>>(W_ih, p_wih_h, p_wih_l, H4 * Eq / 4);
    k_split<<<5000, 256>>>(fc_W, p_fcw_h, p_fcw_l, Vq * Hq / 4);
    // 3. x_proj = xs @ W_ih^T + (b_ih+b_hh)   M=2048, N=2048   (HMMA 3-pass)
    k_mma<0><<<dim3(16, 16), 256, SMEM_TOTAL>>>(p_xs_h, p_xs_l, p_wih_h, p_wih_l,
                                                p_bias, p_xproj, H4);
    // 4. LSTM scan: one persistent kernel, 32 steps with device-wide barrier
    k_scan<<<128, 256>>>(W_hh);
    // 5. logits = h_seq @ fc_W^T + fc_b, scattered to [B][T][V]   M=2048, N=10000
    k_mma<1><<<dim3((Vq + 127) / 128, 16), 256, SMEM_TOTAL>>>(p_hs_h, p_hs_l, p_fcw_h, p_fcw_l,
                                                              fc_b, out, Vq);
}

// round 10
// speedup vs baseline: 3.9051x; 1.6405x over previous
#include <cuda_runtime.h>
#include <cuda_bf16.h>
#include <math.h>
#include <stdint.h>

#define Bq 64
#define Tq 32
#define Eq 512
#define Hq 512
#define H4 2048
#define Vq 10000

// ---------------- scratch (static device globals; no allocation) ----------------
__device__ __nv_bfloat16 g_xs_h[Tq * Bq * Eq];    // xs split hi   2MB
__device__ __nv_bfloat16 g_xs_l[Tq * Bq * Eq];    // xs split lo   2MB
__device__ __nv_bfloat16 g_wih_h[H4 * Eq];        // W_ih split    2MB
__device__ __nv_bfloat16 g_wih_l[H4 * Eq];
__device__ __nv_bfloat16 g_fcw_h[Vq * Hq];        // fc_W split   10MB
__device__ __nv_bfloat16 g_fcw_l[Vq * Hq];
__device__ __nv_bfloat16 g_hs_h[Tq * Bq * Hq];    // h_seq split   2MB
__device__ __nv_bfloat16 g_hs_l[Tq * Bq * Hq];
__device__ float g_xproj[Tq * Bq * H4];           // [T][B][4H]   16MB
__device__ float g_bias[H4];                      // b_ih + b_hh
__device__ int   g_tok[Bq * Tq];                  // decoded caption tokens
__device__ unsigned g_cnt;                        // grid barrier counter
__device__ volatile unsigned g_gen;               // grid barrier generation

// ---------------- helpers -------------------------------------------------------
__device__ __forceinline__ uint32_t smem_u32(const void* p) {
    uint32_t a;
    asm("{ .reg .u64 t; cvta.to.shared.u64 t, %1; cvt.u32.u64 %0, t; }" : "=r"(a) : "l"(p));
    return a;
}

#define LDSM4(r, addr) \
    asm volatile("ldmatrix.sync.aligned.m8n8.x4.shared.b16 {%0,%1,%2,%3}, [%4];" \
        : "=r"((r)[0]), "=r"((r)[1]), "=r"((r)[2]), "=r"((r)[3]) : "r"(addr))

#define MMA16816(d, a, b) \
    asm volatile("mma.sync.aligned.m16n8k16.row.col.f32.bf16.bf16.f32 " \
        "{%0,%1,%2,%3}, {%4,%5,%6,%7}, {%8,%9}, {%0,%1,%2,%3};" \
        : "+f"((d)[0]), "+f"((d)[1]), "+f"((d)[2]), "+f"((d)[3]) \
        : "r"((a)[0]), "r"((a)[1]), "r"((a)[2]), "r"((a)[3]), "r"((b)[0]), "r"((b)[1]))

__device__ __forceinline__ void split1(float x, __nv_bfloat16& h, __nv_bfloat16& l) {
    h = __float2bfloat16(x);
    l = __float2bfloat16(x - __bfloat162float(h));
}

// ---------------- token decode: handle captions as int32 OR int64 ---------------
__global__ void k_tok(const int* __restrict__ cap32) {
    __shared__ int s_or;
    if (threadIdx.x == 0) s_or = 0;
    __syncthreads();
    int tid = threadIdx.x;                 // 1024 threads
    if (cap32[2 * tid + 1] != 0) atomicOr(&s_or, 1);
    __syncthreads();
    bool is64 = (s_or == 0);
    for (int i = tid; i < Bq * Tq; i += 1024) {
        int tok = is64 ? cap32[2 * i] : cap32[i];
        tok = tok < 0 ? 0 : (tok >= Vq ? Vq - 1 : tok);
        g_tok[i] = tok;
    }
}

// ---------------- prep: gather embeddings (split to bf16 hi/lo), bias, barrier --
__global__ void k_prep(const float* __restrict__ feat,
                       const float* __restrict__ embW,
                       const float* __restrict__ b_ih,
                       const float* __restrict__ b_hh) {
    int i = blockIdx.x * blockDim.x + threadIdx.x;   // 262144: one float4 of xs each
    int e4 = i & 127;            // E/4 = 128
    int b  = (i >> 7) & 63;
    int t  = i >> 13;
    float4 v;
    if (t == 0) {
        v = ((const float4*)feat)[b * 128 + e4];
    } else {
        int tok = g_tok[b * Tq + t];
        v = ((const float4*)embW)[(size_t)tok * 128 + e4];
    }
    __nv_bfloat16 h0, l0, h1, l1, h2, l2, h3, l3;
    split1(v.x, h0, l0); split1(v.y, h1, l1);
    split1(v.z, h2, l2); split1(v.w, h3, l3);
    ((ushort4*)g_xs_h)[i] = make_ushort4(__bfloat16_as_ushort(h0), __bfloat16_as_ushort(h1),
                                         __bfloat16_as_ushort(h2), __bfloat16_as_ushort(h3));
    ((ushort4*)g_xs_l)[i] = make_ushort4(__bfloat16_as_ushort(l0), __bfloat16_as_ushort(l1),
                                         __bfloat16_as_ushort(l2), __bfloat16_as_ushort(l3));

    if (i < H4) g_bias[i] = b_ih[i] + b_hh[i];
    if (i == 0) { g_cnt = 0; g_gen = 0; }
}

// ---------------- generic fp32 -> bf16 hi/lo split -------------------------------
__global__ void k_split(const float* __restrict__ in, __nv_bfloat16* __restrict__ oh,
                        __nv_bfloat16* __restrict__ ol, int n4) {
    int i = blockIdx.x * blockDim.x + threadIdx.x;
    if (i >= n4) return;
    float4 v = ((const float4*)in)[i];
    __nv_bfloat16 h0, l0, h1, l1, h2, l2, h3, l3;
    split1(v.x, h0, l0); split1(v.y, h1, l1);
    split1(v.z, h2, l2); split1(v.w, h3, l3);
    ((ushort4*)oh)[i] = make_ushort4(__bfloat16_as_ushort(h0), __bfloat16_as_ushort(h1),
                                     __bfloat16_as_ushort(h2), __bfloat16_as_ushort(h3));
    ((ushort4*)ol)[i] = make_ushort4(__bfloat16_as_ushort(l0), __bfloat16_as_ushort(l1),
                                     __bfloat16_as_ushort(l2), __bfloat16_as_ushort(l3));
}

// ---------------- HMMA bf16 3-pass GEMM: C = A*B^T + bias -----------------------
// Block tile 128x128, BK=32, 8 warps of 32m x 64n. cp.async double-buffered smem,
// XOR-16B swizzle, ldmatrix.x4 fragments, mma.sync.m16n8k16 (baseline PTX ISA).
// Precision: A=Ah+Al, B=Bh+Bl (bf16); acc += Ah*Bh + Ah*Bl + Al*Bh in fp32.
// MODE 0: C[m*2048 + n]                          (x_proj)
// MODE 1: out[(m&63)*T*V + (m>>6)*V + n], n<Nn   (fc logits scatter to [B][T][V])
#define TILE_A_H 0
#define TILE_A_L 8192
#define TILE_B_H 16384
#define TILE_B_L 24576
#define BUF_STRIDE 32768
#define SMEM_TOTAL 65536
#define NKB 16

template <int MODE>
__global__ void __launch_bounds__(256, 1)
k_mma(const __nv_bfloat16* __restrict__ Ah, const __nv_bfloat16* __restrict__ Al,
      const __nv_bfloat16* __restrict__ Bh, const __nv_bfloat16* __restrict__ Bl,
      const float* __restrict__ bias, float* __restrict__ C, int Nn) {
    extern __shared__ char smem[];
    const uint32_t sb = smem_u32(smem);
    const int tid  = threadIdx.x;
    const int lane = tid & 31;
    const int wid  = tid >> 5;
    const int bm = blockIdx.y * 128;
    const int bn = blockIdx.x * 128;
    const int m0 = (wid & 3) * 32;     // warp m-offset within tile
    const int n0 = (wid >> 2) * 64;    // warp n-offset within tile

    float acc[2][8][4];
    #pragma unroll
    for (int ma = 0; ma < 2; ma++)
        #pragma unroll
        for (int na = 0; na < 8; na++)
            #pragma unroll
            for (int q = 0; q < 4; q++) acc[ma][na][q] = 0.f;

    auto fill = [&](int kb, int buf) {
        #pragma unroll
        for (int i = 0; i < 8; i++) {
            int q = tid + i * 256;           // 0..2047 chunk id
            int tile = q >> 9;               // 0..3 (Ah, Al, Bh, Bl)
            int w = q & 511;
            int row = w >> 2, c = w & 3;
            uint32_t dst = sb + (uint32_t)buf * BUF_STRIDE + (uint32_t)tile * 8192
                         + (uint32_t)(row * 64) + (uint32_t)((c ^ (row & 3)) << 4);
            int kc = kb * 32 + c * 8;
            const __nv_bfloat16* src;
            bool valid = true;
            if (tile == 0)      src = Ah + (size_t)(bm + row) * 512 + kc;
            else if (tile == 1) src = Al + (size_t)(bm + row) * 512 + kc;
            else {
                valid = (MODE == 0) || (bn + row) < Nn;
                src = (tile == 2 ? Bh : Bl) + (size_t)(bn + row) * 512 + kc;
            }
            if (valid)
                asm volatile("cp.async.cg.shared.global [%0], [%1], 16;"
                             :: "r"(dst), "l"(src));
            else
                asm volatile("st.shared.v4.b32 [%0], {%1,%1,%1,%1};" :: "r"(dst), "r"(0u));
        }
    };

    auto compute = [&](int buf) {
        const uint32_t bb = sb + (uint32_t)buf * BUF_STRIDE;
        #pragma unroll
        for (int ka = 0; ka < 2; ka++) {
            uint32_t bhf[8][2], blf[8][2];
            const int brow0 = n0 + (lane & 7) + ((lane >> 4) & 1) * 8;
            const int bck = ka * 2 + ((lane >> 3) & 1);
            #pragma unroll
            for (int g = 0; g < 4; g++) {
                int row = brow0 + g * 16;
                uint32_t off = (uint32_t)(row * 64) + (uint32_t)((bck ^ (row & 3)) << 4);
                uint32_t r[4];
                LDSM4(r, bb + TILE_B_H + off);
                bhf[2*g][0] = r[0]; bhf[2*g][1] = r[1];
                bhf[2*g+1][0] = r[2]; bhf[2*g+1][1] = r[3];
                LDSM4(r, bb + TILE_B_L + off);
                blf[2*g][0] = r[0]; blf[2*g][1] = r[1];
                blf[2*g+1][0] = r[2]; blf[2*g+1][1] = r[3];
            }
            uint32_t ahf[2][4], alf[2][4];
            const int arow0 = m0 + (lane & 15);
            const int ack = ka * 2 + (lane >> 4);
            #pragma unroll
            for (int ma = 0; ma < 2; ma++) {
                int row = arow0 + ma * 16;
                uint32_t off = (uint32_t)(row * 64) + (uint32_t)((ack ^ (row & 3)) << 4);
                LDSM4(ahf[ma], bb + TILE_A_H + off);
                LDSM4(alf[ma], bb + TILE_A_L + off);
            }
            #pragma unroll
            for (int ma = 0; ma < 2; ma++)
                #pragma unroll
                for (int na = 0; na < 8; na++) {
                    MMA16816(acc[ma][na], ahf[ma], bhf[na]);   // hi*hi
                    MMA16816(acc[ma][na], ahf[ma], blf[na]);   // hi*lo
                    MMA16816(acc[ma][na], alf[ma], bhf[na]);   // lo*hi
                }
        }
    };

    fill(0, 0);
    asm volatile("cp.async.commit_group;" ::: "memory");
    for (int kb = 0; kb < NKB; kb++) {
        if (kb + 1 < NKB) {
            fill(kb + 1, (kb + 1) & 1);
            asm volatile("cp.async.commit_group;" ::: "memory");
            asm volatile("cp.async.wait_group 1;" ::: "memory");
        } else {
            asm volatile("cp.async.wait_group 0;" ::: "memory");
        }
        __syncthreads();
        compute(kb & 1);
        __syncthreads();
    }

    #pragma unroll
    for (int ma = 0; ma < 2; ma++)
        #pragma unroll
        for (int na = 0; na < 8; na++) {
            int mrow0 = bm + m0 + ma * 16 + (lane >> 2);
            int n = bn + n0 + na * 8 + (lane & 3) * 2;
            if (MODE == 1 && n >= Nn) continue;
            float2 bv = *(const float2*)(bias + n);
            #pragma unroll
            for (int half = 0; half < 2; half++) {
                int m = mrow0 + half * 8;
                size_t base = (MODE == 0)
                    ? (size_t)m * 2048 + n
                    : (size_t)(m & 63) * (Tq * (size_t)Vq) + (size_t)(m >> 6) * Vq + n;
                float2 o;
                o.x = acc[ma][na][half * 2 + 0] + bv.x;
                o.y = acc[ma][na][half * 2 + 1] + bv.y;
                *(float2*)(C + base) = o;
            }
        }
}

// ---------------- persistent tensor-core LSTM scan ------------------------------
// 128 blocks x 128 threads. Block owns 4 j-columns x 4 gates = 16 W_hh rows,
// split to bf16 hi/lo ONCE in smem. Per step: stage h(t-1) hi/lo (g_hs arrays)
// via cp.async, 3-pass HMMA (64x16x512), shfl gate exchange, elementwise update.
// smem: A_hi[64K) A_lo[64K,128K) W_hi[128K,144K) W_lo[144K,160K)
#define SC_A_L   65536
#define SC_W_H   131072
#define SC_W_L   147456
#define SC_SMEM  163840

__device__ __forceinline__ void gridsync(unsigned gen) {
    __syncthreads();
    if (threadIdx.x == 0) {
        __threadfence();
        if (atomicAdd(&g_cnt, 1) == 127u) {
            g_cnt = 0;
            __threadfence();
            g_gen = gen;
        } else {
            while (g_gen != gen) __nanosleep(32);
            __threadfence();
        }
    }
    __syncthreads();
}

__global__ void __launch_bounds__(128, 1) k_scan(const float* __restrict__ Whh) {
    extern __shared__ char smem[];
    const uint32_t sb = smem_u32(smem);
    const int tid  = threadIdx.x;
    const int lane = tid & 31;
    const int w    = tid >> 5;          // warp 0..3 -> m-rows 16w..16w+15
    const int j0   = blockIdx.x * 4;

    // ---- load + split W_hh slice into smem (once). row = g*4+jl -> Whh row g*512+j0+jl
    for (int idx = tid; idx < 16 * 512; idx += 128) {
        int row = idx >> 9, k = idx & 511;
        int grow = (row >> 2) * Hq + j0 + (row & 3);
        float wv = Whh[(size_t)grow * Hq + k];
        __nv_bfloat16 wh, wl;
        split1(wv, wh, wl);
        int kb = k >> 5, c = (k >> 3) & 3, e = k & 7;
        uint32_t off = (uint32_t)(kb * 1024 + row * 64 + ((c ^ (row & 3)) << 4) + e * 2);
        *(__nv_bfloat16*)(smem + SC_W_H + off) = wh;
        *(__nv_bfloat16*)(smem + SC_W_L + off) = wl;
    }
    __syncthreads();

    // ---- static epilogue mapping per lane
    const int type = lane & 3;
    const int own  = (type >= 2) ? 1 : 0;        // own acc column within pair
    const int snd  = 1 - own;
    const int jm   = (type & 1) * 2 + own;       // my j within block's 4
    const int jg   = j0 + jm;                    // global j
    const int b0   = w * 16 + (lane >> 2);       // my two batches: b0, b0+8

    float c0 = 0.f, c1 = 0.f;                    // cell state for (b0, jg), (b0+8, jg)

    for (int t = 0; t < Tq; t++) {
        float acc[2][4];
        #pragma unroll
        for (int na = 0; na < 2; na++)
            #pragma unroll
            for (int q = 0; q < 4; q++) acc[na][q] = 0.f;

        if (t > 0) {
            // stage h(t-1) hi/lo: 8192 16B chunks, 64 per thread
            const __nv_bfloat16* hsh = g_hs_h + (size_t)(t - 1) * Bq * Hq;
            const __nv_bfloat16* hsl = g_hs_l + (size_t)(t - 1) * Bq * Hq;
            #pragma unroll
            for (int i = 0; i < 64; i++) {
                int q = tid + i * 128;           // 0..8191
                int sel = q >> 12;               // 0 = hi, 1 = lo
                int v = q & 4095;
                int row = v >> 6, kb = (v >> 2) & 15, c = v & 3;
                uint32_t dst = sb + (uint32_t)sel * SC_A_L
                             + (uint32_t)(kb * 4096 + row * 64 + ((c ^ (row & 3)) << 4));
                const __nv_bfloat16* src = (sel ? hsl : hsh) + row * 512 + kb * 32 + c * 8;
                asm volatile("cp.async.cg.shared.global [%0], [%1], 16;"
                             :: "r"(dst), "l"(src));
            }
            asm volatile("cp.async.commit_group;" ::: "memory");
            asm volatile("cp.async.wait_group 0;" ::: "memory");
            __syncthreads();

            // 3-pass MMA: M=64 (warp m16), N=16, K=512
            const int arow = w * 16 + (lane & 15);
            const int brow = (lane & 7) + ((lane >> 4) & 1) * 8;
            #pragma unroll 4
            for (int kb = 0; kb < 16; kb++) {
                #pragma unroll
                for (int ka = 0; ka < 2; ka++) {
                    const int ack = ka * 2 + (lane >> 4);
                    const int bck = ka * 2 + ((lane >> 3) & 1);
                    uint32_t aoff = (uint32_t)(kb * 4096 + arow * 64 + ((ack ^ (arow & 3)) << 4));
                    uint32_t boff = (uint32_t)(kb * 1024 + brow * 64 + ((bck ^ (brow & 3)) << 4));
                    uint32_t ahf[4], alf[4], bh4[4], bl4[4];
                    LDSM4(ahf, sb + aoff);
                    LDSM4(alf, sb + SC_A_L + aoff);
                    LDSM4(bh4, sb + SC_W_H + boff);
                    LDSM4(bl4, sb + SC_W_L + boff);
                    uint32_t bh0[2] = {bh4[0], bh4[1]}, bh1[2] = {bh4[2], bh4[3]};
                    uint32_t bl0[2] = {bl4[0], bl4[1]}, bl1[2] = {bl4[2], bl4[3]};
                    MMA16816(acc[0], ahf, bh0);
                    MMA16816(acc[0], ahf, bl0);
                    MMA16816(acc[0], alf, bh0);
                    MMA16816(acc[1], ahf, bh1);
                    MMA16816(acc[1], ahf, bl1);
                    MMA16816(acc[1], alf, bh1);
                }
            }
        }

        // ---- gate exchange: pair lanes l <-> l^2 hold complementary gates
        const float* xp = g_xproj + (size_t)t * Bq * H4;
        float* csel[2] = {&c0, &c1};
        #pragma unroll
        for (int half = 0; half < 2; half++) {
            int b = b0 + half * 8;
            float o0 = acc[0][half * 2 + own];   // my gate (g0 or g1) at my j
            float o1 = acc[1][half * 2 + own];   // my gate (g2 or g3) at my j
            float s0 = acc[0][half * 2 + snd];   // partner's j, my gates
            float s1 = acc[1][half * 2 + snd];
            float r0 = __shfl_xor_sync(0xFFFFFFFF, s0, 2);
            float r1 = __shfl_xor_sync(0xFFFFFFFF, s1, 2);
            float gi = (type < 2 ? o0 : r0);
            float gf = (type < 2 ? r0 : o0);
            float gg = (type < 2 ? o1 : r1);
            float go = (type < 2 ? r1 : o1);
            const float* xpb = xp + (size_t)b * H4 + jg;
            gi += __ldg(xpb);
            gf += __ldg(xpb + 512);
            gg += __ldg(xpb + 1024);
            go += __ldg(xpb + 1536);
            float si = 1.f / (1.f + __expf(-gi));
            float sf = 1.f / (1.f + __expf(-gf));
            float so = 1.f / (1.f + __expf(-go));
            float cn = sf * (*csel[half]) + si * tanhf(gg);
            *csel[half] = cn;
            float hn = so * tanhf(cn);
            __nv_bfloat16 hh, hl;
            split1(hn, hh, hl);
            size_t mi = (size_t)(t * Bq + b) * Hq + jg;
            g_hs_h[mi] = hh;
            g_hs_l[mi] = hl;
        }
        if (t < Tq - 1) gridsync((unsigned)(t + 1));
    }
}

// ---------------- launch --------------------------------------------------------
extern "C" void kernel_launch(void* const* d_in, const int* in_sizes, int n_in,
                              void* d_out, int out_size) {
    const float* feat = (const float*)d_in[0];
    const int*   cap  = (const int*)d_in[1];     // int32 OR int64 — detected on device
    const float* embW = (const float*)d_in[2];
    const float* W_ih = (const float*)d_in[3];
    const float* W_hh = (const float*)d_in[4];
    const float* b_ih = (const float*)d_in[5];
    const float* b_hh = (const float*)d_in[6];
    const float* fc_W = (const float*)d_in[7];
    const float* fc_b = (const float*)d_in[8];
    float* out = (float*)d_out;

    static int smem_set = 0;
    if (!smem_set) {
        cudaFuncSetAttribute(k_mma<0>, cudaFuncAttributeMaxDynamicSharedMemorySize, SMEM_TOTAL);
        cudaFuncSetAttribute(k_mma<1>, cudaFuncAttributeMaxDynamicSharedMemorySize, SMEM_TOTAL);
        cudaFuncSetAttribute(k_scan,   cudaFuncAttributeMaxDynamicSharedMemorySize, SC_SMEM);
        smem_set = 1;
    }

    __nv_bfloat16 *p_xs_h, *p_xs_l, *p_wih_h, *p_wih_l, *p_fcw_h, *p_fcw_l, *p_hs_h, *p_hs_l;
    float *p_xproj, *p_bias;
    cudaGetSymbolAddress((void**)&p_xs_h,  g_xs_h);
    cudaGetSymbolAddress((void**)&p_xs_l,  g_xs_l);
    cudaGetSymbolAddress((void**)&p_wih_h, g_wih_h);
    cudaGetSymbolAddress((void**)&p_wih_l, g_wih_l);
    cudaGetSymbolAddress((void**)&p_fcw_h, g_fcw_h);
    cudaGetSymbolAddress((void**)&p_fcw_l, g_fcw_l);
    cudaGetSymbolAddress((void**)&p_hs_h,  g_hs_h);
    cudaGetSymbolAddress((void**)&p_hs_l,  g_hs_l);
    cudaGetSymbolAddress((void**)&p_xproj, g_xproj);
    cudaGetSymbolAddress((void**)&p_bias,  g_bias);

    // order chosen so the profiler's fixed capture slot (4th launch) hits k_mma<0>
    k_tok<<<1, 1024>>>(cap);                                         // 1
    k_prep<<<1024, 256>>>(feat, embW, b_ih, b_hh);                   // 2
    k_split<<<1024, 256>>>(W_ih, p_wih_h, p_wih_l, H4 * Eq / 4);     // 3
    k_mma<0><<<dim3(16, 16), 256, SMEM_TOTAL>>>(p_xs_h, p_xs_l, p_wih_h, p_wih_l,
                                                p_bias, p_xproj, H4);// 4
    k_split<<<5000, 256>>>(fc_W, p_fcw_h, p_fcw_l, Vq * Hq / 4);     // 5
    k_scan<<<128, 128, SC_SMEM>>>(W_hh);                             // 6
    k_mma<1><<<dim3((Vq + 127) / 128, 16), 256, SMEM_TOTAL>>>(p_hs_h, p_hs_l, p_fcw_h, p_fcw_l,
                                                              fc_b, out, Vq);  // 7
}